// round 13
// baseline (speedup 1.0000x reference)
#include <cuda_runtime.h>
#include <cuda_bf16.h>
#include <cstdint>

#define Nn 8192
#define Dd 256
#define Kn 10
#define NTILE 64                      // Nn / 128
#define NTRI  (NTILE * (NTILE + 1) / 2)   // 2080
#define NFULL 2072                    // 296 * 7 : perfectly filled waves
#define NSPLIT (NTRI - NFULL)         // 8 tiles, split in K halves

// ---------------- scratch (device globals) ---------------------------------
__device__ float g_Xsq[Nn];
__device__ float2 g_cand[(size_t)Nn * NTILE * Kn];   // 42 MB: [row][tile][10]
__device__ float g_rowsum[Nn];
__device__ int   g_done = 0;
__device__ float g_part[NSPLIT * 256 * 64];          // 512 KB split-K partials
__device__ int   g_flag[NSPLIT];
// K-chunk-major bf16 halves: [chunk c (32 elems)][row][4 x uint4]
__device__ uint4 g_Xhi4[Nn * Dd / 8];
__device__ uint4 g_Xlo4[Nn * Dd / 8];

// ---------------- helpers --------------------------------------------------
__device__ __forceinline__ uint32_t smem_u32(const void* p) {
    uint32_t a;
    asm("{ .reg .u64 t; cvta.to.shared.u64 t, %1; cvt.u32.u64 %0, t; }" : "=r"(a) : "l"(p));
    return a;
}
__device__ __forceinline__ void cp16(uint32_t s, const void* g) {
    asm volatile("cp.async.cg.shared.global [%0], [%1], 16;" :: "r"(s), "l"(g));
}
#define CP_COMMIT() asm volatile("cp.async.commit_group;" ::: "memory")
#define CP_WAIT(n)  asm volatile("cp.async.wait_group %0;" :: "n"(n) : "memory")

__device__ __forceinline__ void ldsm_x4(uint32_t& r0, uint32_t& r1, uint32_t& r2, uint32_t& r3, uint32_t a) {
    asm volatile("ldmatrix.sync.aligned.m8n8.x4.shared.b16 {%0,%1,%2,%3}, [%4];"
                 : "=r"(r0), "=r"(r1), "=r"(r2), "=r"(r3) : "r"(a));
}
__device__ __forceinline__ void mma16816(float* d, const uint32_t* a, const uint32_t* b) {
    asm volatile("mma.sync.aligned.m16n8k16.row.col.f32.bf16.bf16.f32 "
                 "{%0,%1,%2,%3}, {%4,%5,%6,%7}, {%8,%9}, {%0,%1,%2,%3};"
                 : "+f"(d[0]), "+f"(d[1]), "+f"(d[2]), "+f"(d[3])
                 : "r"(a[0]), "r"(a[1]), "r"(a[2]), "r"(a[3]), "r"(b[0]), "r"(b[1]));
}

// register-resident sorted-10 insert (static indices only -> no local mem)
#define TOP10_INSERT(s, j, v, id)                                              \
    if ((s) < v[9]) {                                                          \
        v[9] = (s); id[9] = (j);                                               \
        _Pragma("unroll")                                                      \
        for (int _k = 8; _k >= 0; --_k) {                                      \
            if (v[_k + 1] < v[_k]) {                                           \
                float _tv = v[_k]; v[_k] = v[_k + 1]; v[_k + 1] = _tv;         \
                int _ti = id[_k]; id[_k] = id[_k + 1]; id[_k + 1] = _ti;       \
            }                                                                  \
        }                                                                      \
    }

// 64B-row XOR swizzle: 16B unit u of row r stored at u' = u ^ ((r>>1)&3)
__device__ __forceinline__ uint32_t swz_off(int row, int u) {
    return (uint32_t)(row * 64 + ((u ^ ((row >> 1) & 3)) << 4));
}

// ---------------- kernel 0: fp32 -> bf16 hi/lo split + fused Xsq -----------
__global__ void convert_kernel(const float* __restrict__ X) {
    int i = blockIdx.x * 256 + threadIdx.x;    // uint4 index, Nn*32 total
    int lane = threadIdx.x & 31;
    int r = i >> 5;                            // row (one row per warp)
    int q = i & 31;                            // uint4 within row (== lane)
    int c = q >> 2;                            // k-chunk (32 elems)
    int p = q & 3;                             // uint4 within chunk
    const float4* xp = reinterpret_cast<const float4*>(X) + (size_t)i * 2;
    float4 a = xp[0], b = xp[1];
    float v[8] = {a.x, a.y, a.z, a.w, b.x, b.y, b.z, b.w};
    __nv_bfloat16 hi[8], lo[8];
    float s = 0.0f;
    #pragma unroll
    for (int k = 0; k < 8; ++k) {
        s = fmaf(v[k], v[k], s);
        hi[k] = __float2bfloat16(v[k]);
        lo[k] = __float2bfloat16(v[k] - __bfloat162float(hi[k]));
    }
    size_t dst = ((size_t)c * Nn + r) * 4 + p;
    g_Xhi4[dst] = *reinterpret_cast<uint4*>(hi);
    g_Xlo4[dst] = *reinterpret_cast<uint4*>(lo);
    #pragma unroll
    for (int o = 16; o > 0; o >>= 1) s += __shfl_xor_sync(0xFFFFFFFFu, s, o);
    if (lane == 0) g_Xsq[r] = s;
}

// ---------------- kernel 2: symmetric HMMA GEMM + fused per-tile top-10 ----
#define BKc     32
#define NCHUNK  (Dd / BKc)            // 8
#define TILE_B  (128 * 64)            // 8192 B (64B swizzled rows)
#define STAGE_B (4 * TILE_B)          // 32768: Ahi, Alo, Bhi, Blo
#define SMEM_DYN (3 * STAGE_B)        // 98304 B (>= 128*132*4 = 67584 stage)

__global__ void __launch_bounds__(256, 2) gemm_mma_kernel() {
    extern __shared__ char dynsm[];
    __shared__ __align__(16) float sXsq[256];
    const uint32_t smb = smem_u32(dynsm);

    const int t = threadIdx.x, wid = t >> 5, lane = t & 31;

    // work decode: first NFULL blocks = full tiles; rest = K-split half pairs
    const int bid = blockIdx.x;
    int tidx, cbeg, cend, khalf = 0, t8 = 0;
    bool split = (bid >= NFULL);
    if (!split) { tidx = bid; cbeg = 0; cend = NCHUNK; }
    else {
        int s = bid - NFULL;
        t8 = s >> 1;
        tidx = NFULL + t8;
        khalf = s & 1;
        cbeg = khalf * (NCHUNK / 2);
        cend = cbeg + (NCHUNK / 2);
    }

    // triangular decode: tidx -> (bi, bj), bi >= bj
    int bi = (int)((-1.0f + sqrtf(1.0f + 8.0f * (float)tidx)) * 0.5f);
    while ((bi + 1) * (bi + 2) / 2 <= tidx) ++bi;
    while (bi * (bi + 1) / 2 > tidx) --bi;
    int bj = tidx - bi * (bi + 1) / 2;
    const int i0 = bi * 128, j0 = bj * 128;

    const int warpM = wid & 1, warpN = wid >> 1;
    const int lrow = t >> 1, lh = t & 1;

    float acc[4][4][4];
    #pragma unroll
    for (int mt = 0; mt < 4; ++mt)
        #pragma unroll
        for (int nt = 0; nt < 4; ++nt)
            #pragma unroll
            for (int q = 0; q < 4; ++q) acc[mt][nt][q] = 0.0f;

    const int arow = (lane & 15), au = (lane >> 4);
    const int bm = lane >> 3;
    const int brow2 = 8 * (bm >> 1) + (lane & 7);
    const int bu = (bm & 1);

    auto issue_stage = [&](int c, int buf) {
        uint32_t st = smb + buf * STAGE_B;
        size_t cb = (size_t)c * Nn * 4;
        size_t ga = cb + (size_t)(i0 + lrow) * 4 + lh * 2;
        size_t gb = cb + (size_t)(j0 + lrow) * 4 + lh * 2;
        #pragma unroll
        for (int q = 0; q < 2; ++q) {
            uint32_t off = swz_off(lrow, lh * 2 + q);
            cp16(st + 0 * TILE_B + off, g_Xhi4 + ga + q);
            cp16(st + 1 * TILE_B + off, g_Xlo4 + ga + q);
            cp16(st + 2 * TILE_B + off, g_Xhi4 + gb + q);
            cp16(st + 3 * TILE_B + off, g_Xlo4 + gb + q);
        }
        CP_COMMIT();
    };

    issue_stage(cbeg, 0);
    issue_stage(cbeg + 1, 1);
    if (t < 128) sXsq[t] = g_Xsq[j0 + t];
    else         sXsq[t] = g_Xsq[i0 + (t - 128)];

    int buf = 0;
    for (int c = cbeg; c < cend; ++c) {
        if (c + 1 < cend) { CP_WAIT(1); } else { CP_WAIT(0); }
        __syncthreads();
        if (c + 2 < cend) {
            int nbuf = buf + 2; if (nbuf >= 3) nbuf -= 3;
            issue_stage(c + 2, nbuf);
        }

        const uint32_t st = smb + buf * STAGE_B;
        #pragma unroll
        for (int ks = 0; ks < 2; ++ks) {
            uint32_t Ahi[4][4], Alo[4][4];
            #pragma unroll
            for (int mt = 0; mt < 4; ++mt) {
                uint32_t a = st + swz_off(warpM * 64 + mt * 16 + arow, ks * 2 + au);
                ldsm_x4(Ahi[mt][0], Ahi[mt][1], Ahi[mt][2], Ahi[mt][3], a + 0 * TILE_B);
                ldsm_x4(Alo[mt][0], Alo[mt][1], Alo[mt][2], Alo[mt][3], a + 1 * TILE_B);
            }
            #pragma unroll
            for (int p = 0; p < 2; ++p) {
                uint32_t ba = st + swz_off(warpN * 32 + p * 16 + brow2, ks * 2 + bu);
                uint32_t Bh[4], Bl[4];
                ldsm_x4(Bh[0], Bh[1], Bh[2], Bh[3], ba + 2 * TILE_B);
                ldsm_x4(Bl[0], Bl[1], Bl[2], Bl[3], ba + 3 * TILE_B);
                #pragma unroll
                for (int mt = 0; mt < 4; ++mt) {
                    mma16816(acc[mt][2 * p],     Ahi[mt], Bh + 0);
                    mma16816(acc[mt][2 * p],     Alo[mt], Bh + 0);
                    mma16816(acc[mt][2 * p],     Ahi[mt], Bl + 0);
                    mma16816(acc[mt][2 * p + 1], Ahi[mt], Bh + 2);
                    mma16816(acc[mt][2 * p + 1], Alo[mt], Bh + 2);
                    mma16816(acc[mt][2 * p + 1], Ahi[mt], Bl + 2);
                }
            }
        }
        if (++buf >= 3) buf -= 3;
    }

    float* af = &acc[0][0][0];

    if (split) {
        if (khalf == 0) {
            // write partial tile (thread-identical layout), release flag, exit
            float4* dst = reinterpret_cast<float4*>(&g_part[(t8 * 256 + t) * 64]);
            #pragma unroll
            for (int i = 0; i < 16; ++i)
                dst[i] = *reinterpret_cast<float4*>(af + 4 * i);
            __syncthreads();
            if (t == 0) { __threadfence(); atomicExch(&g_flag[t8], 1); }
            return;
        }
        // khalf == 1: acquire partner's partial, accumulate
        if (t == 0) {
            while (atomicAdd(&g_flag[t8], 0) == 0) __nanosleep(64);
            __threadfence();
        }
        __syncthreads();
        const float4* src = reinterpret_cast<const float4*>(&g_part[(t8 * 256 + t) * 64]);
        #pragma unroll
        for (int i = 0; i < 16; ++i) {
            float4 p4 = src[i];
            af[4 * i + 0] += p4.x; af[4 * i + 1] += p4.y;
            af[4 * i + 2] += p4.z; af[4 * i + 3] += p4.w;
        }
    }

    __syncthreads();   // all warps done with smem stages before aliasing as stg

    // ---- stage dot tile in smem (stride 132: float4-aligned, conflict-free)
    float* stg = reinterpret_cast<float*>(dynsm);      // 128 x 132 floats
    const int gq = lane >> 2, tig = lane & 3;
    #pragma unroll
    for (int nt = 0; nt < 4; ++nt) {
        const int col = warpN * 32 + nt * 8 + tig * 2;
        #pragma unroll
        for (int mt = 0; mt < 4; ++mt) {
            const int r0 = warpM * 64 + mt * 16 + gq;
            float* d = acc[mt][nt];
            stg[r0 * 132 + col]           = d[0];
            stg[r0 * 132 + col + 1]       = d[1];
            stg[(r0 + 8) * 132 + col]     = d[2];
            stg[(r0 + 8) * 132 + col + 1] = d[3];
        }
    }
    __syncthreads();

    // ---- fused per-tile top-10 scan ----
    const bool trans = (t >= 128);
    if (!trans || bi != bj) {
        const int r = t & 127;
        float v[Kn]; int id[Kn];
        #pragma unroll
        for (int k = 0; k < Kn; ++k) { v[k] = 3.4e38f; id[k] = -1; }

        if (!trans) {
            const float4* srow4 = reinterpret_cast<const float4*>(&stg[r * 132]);
            const float4* xsq4  = reinterpret_cast<const float4*>(sXsq);
            const bool diag = (bi == bj);
            #pragma unroll 2
            for (int c4 = 0; c4 < 32; ++c4) {
                float4 dv = srow4[c4];
                float4 xq = xsq4[c4];
                float s0 = xq.x - 2.0f * dv.x;
                float s1 = xq.y - 2.0f * dv.y;
                float s2 = xq.z - 2.0f * dv.z;
                float s3 = xq.w - 2.0f * dv.w;
                int cb = c4 * 4;
                if (diag) {
                    if (cb == r)     s0 = 3.4e38f;
                    if (cb + 1 == r) s1 = 3.4e38f;
                    if (cb + 2 == r) s2 = 3.4e38f;
                    if (cb + 3 == r) s3 = 3.4e38f;
                }
                TOP10_INSERT(s0, j0 + cb,     v, id)
                TOP10_INSERT(s1, j0 + cb + 1, v, id)
                TOP10_INSERT(s2, j0 + cb + 2, v, id)
                TOP10_INSERT(s3, j0 + cb + 3, v, id)
            }
            float2* dst = &g_cand[((size_t)(i0 + r) * NTILE + bj) * Kn];
            #pragma unroll
            for (int k = 0; k < Kn; ++k)
                dst[k] = make_float2(v[k], __int_as_float(id[k]));
        } else {
            #pragma unroll 4
            for (int c = 0; c < 128; ++c) {
                float s = sXsq[128 + c] - 2.0f * stg[c * 132 + r];
                TOP10_INSERT(s, i0 + c, v, id)
            }
            float2* dst = &g_cand[((size_t)(j0 + r) * NTILE + bi) * Kn];
            #pragma unroll
            for (int k = 0; k < Kn; ++k)
                dst[k] = make_float2(v[k], __int_as_float(id[k]));
        }
    }

    // reset split flag for next graph replay
    if (split && khalf == 1 && t == 0) g_flag[t8] = 0;
}

// ---------------- kernel 3: fused merge + loss + final reduction -----------
// key = (ordered(val) << 32) | idx : smaller d2 first, tie -> smaller idx.
__device__ __forceinline__ uint64_t pack_key(float2 p) {
    uint32_t u = __float_as_uint(p.x);
    u = (u & 0x80000000u) ? ~u : (u | 0x80000000u);
    return ((uint64_t)u << 32) | (uint32_t)__float_as_int(p.y);
}
__device__ __forceinline__ float unpack_val(uint64_t k) {
    uint32_t u = (uint32_t)(k >> 32);
    u = (u & 0x80000000u) ? (u & 0x7fffffffu) : ~u;
    return __uint_as_float(u);
}
#define CEX(a, b) { uint64_t _mn = (a) < (b) ? (a) : (b); \
                    uint64_t _mx = (a) < (b) ? (b) : (a); (a) = _mn; (b) = _mx; }
#define BSORT16(k)                                                             \
    _Pragma("unroll") for (int _d = 8; _d >= 1; _d >>= 1)                      \
        _Pragma("unroll") for (int _i = 0; _i < 16; ++_i)                      \
            if (!(_i & _d)) CEX(k[_i], k[_i + _d])

__global__ void __launch_bounds__(256) topk_loss_kernel(const float* __restrict__ Z,
                                                        float* __restrict__ out) {
    const int lane = threadIdx.x & 31;
    const int row  = blockIdx.x * 8 + (threadIdx.x >> 5);

    // ---- bitonic shuffle merge of 64 sorted-10 lists ----
    uint64_t A[16], K[16];
    {
        const float2* la = &g_cand[((size_t)row * NTILE + lane) * Kn];
        const float2* lb = &g_cand[((size_t)row * NTILE + lane + 32) * Kn];
        uint64_t a[10], b[10];
        #pragma unroll
        for (int k = 0; k < Kn; ++k) { a[k] = pack_key(la[k]); b[k] = pack_key(lb[k]); }
        #pragma unroll
        for (int i = 0; i < 6; ++i)  K[i] = a[i];
        #pragma unroll
        for (int i = 6; i < 10; ++i) K[i] = a[i] < b[15 - i] ? a[i] : b[15 - i];
        #pragma unroll
        for (int i = 10; i < 16; ++i) K[i] = b[15 - i];
        BSORT16(K);
    }
    #pragma unroll
    for (int s = 1; s < 32; s <<= 1) {
        uint64_t O[16];
        #pragma unroll
        for (int i = 0; i < 16; ++i)
            O[i] = __shfl_xor_sync(0xFFFFFFFFu, K[i], s);
        #pragma unroll
        for (int i = 0; i < 16; ++i)
            A[i] = K[i] < O[15 - i] ? K[i] : O[15 - i];
        #pragma unroll
        for (int i = 0; i < 16; ++i) K[i] = A[i];
        BSORT16(K);
    }
    // all lanes now hold the global top-16 keys (we use 10)

    // ---- z distances + loss (x_dist from GEMM d2 values) ----
    const float2 zi = reinterpret_cast<const float2*>(Z + (size_t)row * 64)[lane];
    const float xsq_i = g_Xsq[row];
    float xd[Kn], zd[Kn];
    #pragma unroll
    for (int k = 0; k < Kn; ++k) {
        int nb = (int)(uint32_t)(K[k] & 0xffffffffu);
        const float2 zn = reinterpret_cast<const float2*>(Z + (size_t)nb * 64)[lane];
        float d0 = zi.x - zn.x, d1 = zi.y - zn.y;
        float sz = fmaf(d0, d0, d1 * d1);
        #pragma unroll
        for (int o = 16; o > 0; o >>= 1) sz += __shfl_xor_sync(0xFFFFFFFFu, sz, o);
        zd[k] = sqrtf(sz);
        xd[k] = sqrtf(fmaxf(xsq_i + unpack_val(K[k]), 0.0f));
    }
    if (lane == 0) {
        float xm = 0.0f, zm = 0.0f;
        #pragma unroll
        for (int k = 0; k < Kn; ++k) { xm = fmaxf(xm, xd[k]); zm = fmaxf(zm, zd[k]); }
        xm = fmaxf(xm, 1e-8f);
        zm = fmaxf(zm, 1e-8f);
        float s = 0.0f;
        #pragma unroll
        for (int k = 0; k < Kn; ++k) s += fabsf(xd[k] / xm - zd[k] / zm);
        g_rowsum[row] = s;
    }

    // ---- last-block deterministic final reduction ----
    __shared__ int sflag;
    __syncthreads();
    if (threadIdx.x == 0) {
        __threadfence();
        sflag = (atomicAdd(&g_done, 1) == gridDim.x - 1) ? 1 : 0;
    }
    __syncthreads();
    if (sflag) {
        __threadfence();
        __shared__ float sm[256];
        const int t = threadIdx.x;
        float s = 0.0f;
        for (int i = t; i < Nn; i += 256) s += g_rowsum[i];
        sm[t] = s;
        __syncthreads();
        for (int st = 128; st > 0; st >>= 1) {
            if (t < st) sm[t] += sm[t + st];
            __syncthreads();
        }
        if (t == 0) {
            out[0] = sm[0] / (float)(Nn * Kn);
            g_done = 0;                       // reset for next graph replay
        }
    }
}

// ---------------- launch ---------------------------------------------------
extern "C" void kernel_launch(void* const* d_in, const int* in_sizes, int n_in,
                              void* d_out, int out_size) {
    const float* z = (const float*)d_in[0];
    const float* X = (const float*)d_in[1];
    if (n_in >= 2 && in_sizes[0] != Nn * 64) {
        z = (const float*)d_in[1];
        X = (const float*)d_in[0];
    }
    float* out = (float*)d_out;

    cudaFuncSetAttribute(gemm_mma_kernel, cudaFuncAttributeMaxDynamicSharedMemorySize, SMEM_DYN);

    convert_kernel<<<Nn * 32 / 256, 256>>>(X);
    gemm_mma_kernel<<<NFULL + 2 * NSPLIT, 256, SMEM_DYN>>>();
    topk_loss_kernel<<<Nn / 8, 256>>>(z, out);
}

// round 14
// speedup vs baseline: 1.0688x; 1.0688x over previous
#include <cuda_runtime.h>
#include <cuda_bf16.h>
#include <cstdint>

#define Nn 8192
#define Dd 256
#define Kn 10
#define NTILE 64                      // Nn / 128
#define NTRI  (NTILE * (NTILE + 1) / 2)   // 2080

// ---------------- scratch (device globals) ---------------------------------
__device__ float g_Xsq[Nn];
__device__ float2 g_cand[(size_t)Nn * NTILE * Kn];   // 42 MB: [row][tile][10]
__device__ float g_rowsum[Nn];
__device__ int   g_done = 0;
// K-chunk-major bf16 halves: [chunk c (32 elems)][row][4 x uint4]
__device__ uint4 g_Xhi4[Nn * Dd / 8];
__device__ uint4 g_Xlo4[Nn * Dd / 8];

// ---------------- helpers --------------------------------------------------
__device__ __forceinline__ uint32_t smem_u32(const void* p) {
    uint32_t a;
    asm("{ .reg .u64 t; cvta.to.shared.u64 t, %1; cvt.u32.u64 %0, t; }" : "=r"(a) : "l"(p));
    return a;
}
__device__ __forceinline__ void cp16(uint32_t s, const void* g) {
    asm volatile("cp.async.cg.shared.global [%0], [%1], 16;" :: "r"(s), "l"(g));
}
#define CP_COMMIT() asm volatile("cp.async.commit_group;" ::: "memory")
#define CP_WAIT(n)  asm volatile("cp.async.wait_group %0;" :: "n"(n) : "memory")

__device__ __forceinline__ void ldsm_x4(uint32_t& r0, uint32_t& r1, uint32_t& r2, uint32_t& r3, uint32_t a) {
    asm volatile("ldmatrix.sync.aligned.m8n8.x4.shared.b16 {%0,%1,%2,%3}, [%4];"
                 : "=r"(r0), "=r"(r1), "=r"(r2), "=r"(r3) : "r"(a));
}
__device__ __forceinline__ void mma16816(float* d, const uint32_t* a, const uint32_t* b) {
    asm volatile("mma.sync.aligned.m16n8k16.row.col.f32.bf16.bf16.f32 "
                 "{%0,%1,%2,%3}, {%4,%5,%6,%7}, {%8,%9}, {%0,%1,%2,%3};"
                 : "+f"(d[0]), "+f"(d[1]), "+f"(d[2]), "+f"(d[3])
                 : "r"(a[0]), "r"(a[1]), "r"(a[2]), "r"(a[3]), "r"(b[0]), "r"(b[1]));
}

// register-resident sorted-10 insert (static indices only -> no local mem)
#define TOP10_INSERT(s, j, v, id)                                              \
    if ((s) < v[9]) {                                                          \
        v[9] = (s); id[9] = (j);                                               \
        _Pragma("unroll")                                                      \
        for (int _k = 8; _k >= 0; --_k) {                                      \
            if (v[_k + 1] < v[_k]) {                                           \
                float _tv = v[_k]; v[_k] = v[_k + 1]; v[_k + 1] = _tv;         \
                int _ti = id[_k]; id[_k] = id[_k + 1]; id[_k + 1] = _ti;       \
            }                                                                  \
        }                                                                      \
    }

// 64B-row XOR swizzle: 16B unit u of row r stored at u' = u ^ ((r>>1)&3)
__device__ __forceinline__ uint32_t swz_off(int row, int u) {
    return (uint32_t)(row * 64 + ((u ^ ((row >> 1) & 3)) << 4));
}

// ---------------- kernel 0: fp32 -> bf16 hi/lo split + fused Xsq -----------
__global__ void convert_kernel(const float* __restrict__ X) {
    int i = blockIdx.x * 256 + threadIdx.x;    // uint4 index, Nn*32 total
    int lane = threadIdx.x & 31;
    int r = i >> 5;                            // row (one row per warp)
    int q = i & 31;                            // uint4 within row (== lane)
    int c = q >> 2;                            // k-chunk (32 elems)
    int p = q & 3;                             // uint4 within chunk
    const float4* xp = reinterpret_cast<const float4*>(X) + (size_t)i * 2;
    float4 a = xp[0], b = xp[1];
    float v[8] = {a.x, a.y, a.z, a.w, b.x, b.y, b.z, b.w};
    __nv_bfloat16 hi[8], lo[8];
    float s = 0.0f;
    #pragma unroll
    for (int k = 0; k < 8; ++k) {
        s = fmaf(v[k], v[k], s);
        hi[k] = __float2bfloat16(v[k]);
        lo[k] = __float2bfloat16(v[k] - __bfloat162float(hi[k]));
    }
    size_t dst = ((size_t)c * Nn + r) * 4 + p;
    g_Xhi4[dst] = *reinterpret_cast<uint4*>(hi);
    g_Xlo4[dst] = *reinterpret_cast<uint4*>(lo);
    #pragma unroll
    for (int o = 16; o > 0; o >>= 1) s += __shfl_xor_sync(0xFFFFFFFFu, s, o);
    if (lane == 0) g_Xsq[r] = s;
}

// ---------------- kernel 2: symmetric HMMA GEMM + fused per-tile top-10 ----
#define BKc     32
#define NCHUNK  (Dd / BKc)            // 8
#define TILE_B  (128 * 64)            // 8192 B (64B swizzled rows)
#define STAGE_B (4 * TILE_B)          // 32768: Ahi, Alo, Bhi, Blo
#define SMEM_DYN (3 * STAGE_B)        // 98304 B (>= 128*132*4 = 67584 stage)

__global__ void __launch_bounds__(256, 2) gemm_mma_kernel() {
    extern __shared__ char dynsm[];
    __shared__ __align__(16) float sXsq[256];
    const uint32_t smb = smem_u32(dynsm);

    const int t = threadIdx.x, wid = t >> 5, lane = t & 31;

    // triangular decode: blockIdx.x -> (bi, bj), bi >= bj
    int tidx = blockIdx.x;
    int bi = (int)((-1.0f + sqrtf(1.0f + 8.0f * (float)tidx)) * 0.5f);
    while ((bi + 1) * (bi + 2) / 2 <= tidx) ++bi;
    while (bi * (bi + 1) / 2 > tidx) --bi;
    int bj = tidx - bi * (bi + 1) / 2;
    const int i0 = bi * 128, j0 = bj * 128;

    const int warpM = wid & 1, warpN = wid >> 1;
    const int lrow = t >> 1, lh = t & 1;

    float acc[4][4][4];
    #pragma unroll
    for (int mt = 0; mt < 4; ++mt)
        #pragma unroll
        for (int nt = 0; nt < 4; ++nt)
            #pragma unroll
            for (int q = 0; q < 4; ++q) acc[mt][nt][q] = 0.0f;

    const int arow = (lane & 15), au = (lane >> 4);
    const int bm = lane >> 3;
    const int brow2 = 8 * (bm >> 1) + (lane & 7);
    const int bu = (bm & 1);

    auto issue_stage = [&](int c, int buf) {
        uint32_t st = smb + buf * STAGE_B;
        size_t cb = (size_t)c * Nn * 4;
        size_t ga = cb + (size_t)(i0 + lrow) * 4 + lh * 2;
        size_t gb = cb + (size_t)(j0 + lrow) * 4 + lh * 2;
        #pragma unroll
        for (int q = 0; q < 2; ++q) {
            uint32_t off = swz_off(lrow, lh * 2 + q);
            cp16(st + 0 * TILE_B + off, g_Xhi4 + ga + q);
            cp16(st + 1 * TILE_B + off, g_Xlo4 + ga + q);
            cp16(st + 2 * TILE_B + off, g_Xhi4 + gb + q);
            cp16(st + 3 * TILE_B + off, g_Xlo4 + gb + q);
        }
        CP_COMMIT();
    };

    issue_stage(0, 0);
    issue_stage(1, 1);
    if (t < 128) sXsq[t] = g_Xsq[j0 + t];
    else         sXsq[t] = g_Xsq[i0 + (t - 128)];

    int buf = 0;                       // buffer of chunk c
    for (int c = 0; c < NCHUNK; ++c) {
        if (c + 1 < NCHUNK) { CP_WAIT(1); } else { CP_WAIT(0); }
        __syncthreads();
        // prefetch chunk c+2 into the buffer last read at chunk c-1 (drained)
        if (c + 2 < NCHUNK) {
            int nbuf = buf + 2; if (nbuf >= 3) nbuf -= 3;
            issue_stage(c + 2, nbuf);
        }

        const uint32_t st = smb + buf * STAGE_B;
        #pragma unroll
        for (int ks = 0; ks < 2; ++ks) {
            uint32_t Ahi[4][4], Alo[4][4];
            #pragma unroll
            for (int mt = 0; mt < 4; ++mt) {
                uint32_t a = st + swz_off(warpM * 64 + mt * 16 + arow, ks * 2 + au);
                ldsm_x4(Ahi[mt][0], Ahi[mt][1], Ahi[mt][2], Ahi[mt][3], a + 0 * TILE_B);
                ldsm_x4(Alo[mt][0], Alo[mt][1], Alo[mt][2], Alo[mt][3], a + 1 * TILE_B);
            }
            #pragma unroll
            for (int p = 0; p < 2; ++p) {
                uint32_t ba = st + swz_off(warpN * 32 + p * 16 + brow2, ks * 2 + bu);
                uint32_t Bh[4], Bl[4];
                ldsm_x4(Bh[0], Bh[1], Bh[2], Bh[3], ba + 2 * TILE_B);
                ldsm_x4(Bl[0], Bl[1], Bl[2], Bl[3], ba + 3 * TILE_B);
                #pragma unroll
                for (int mt = 0; mt < 4; ++mt) {
                    mma16816(acc[mt][2 * p],     Ahi[mt], Bh + 0);
                    mma16816(acc[mt][2 * p],     Alo[mt], Bh + 0);
                    mma16816(acc[mt][2 * p],     Ahi[mt], Bl + 0);
                    mma16816(acc[mt][2 * p + 1], Ahi[mt], Bh + 2);
                    mma16816(acc[mt][2 * p + 1], Alo[mt], Bh + 2);
                    mma16816(acc[mt][2 * p + 1], Ahi[mt], Bl + 2);
                }
            }
        }
        if (++buf >= 3) buf -= 3;
    }
    __syncthreads();   // all warps done with smem stages before aliasing as stg

    // ---- stage dot tile in smem (stride 132: float4-aligned, conflict-free)
    float* stg = reinterpret_cast<float*>(dynsm);      // 128 x 132 floats
    const int gq = lane >> 2, tig = lane & 3;
    #pragma unroll
    for (int nt = 0; nt < 4; ++nt) {
        const int col = warpN * 32 + nt * 8 + tig * 2;
        #pragma unroll
        for (int mt = 0; mt < 4; ++mt) {
            const int r0 = warpM * 64 + mt * 16 + gq;
            float* d = acc[mt][nt];
            stg[r0 * 132 + col]           = d[0];
            stg[r0 * 132 + col + 1]       = d[1];
            stg[(r0 + 8) * 132 + col]     = d[2];
            stg[(r0 + 8) * 132 + col + 1] = d[3];
        }
    }
    __syncthreads();

    // ---- fused per-tile top-10 scan ----
    const bool trans = (t >= 128);
    if (!trans || bi != bj) {
        const int r = t & 127;
        float v[Kn]; int id[Kn];
        #pragma unroll
        for (int k = 0; k < Kn; ++k) { v[k] = 3.4e38f; id[k] = -1; }

        if (!trans) {
            const float4* srow4 = reinterpret_cast<const float4*>(&stg[r * 132]);
            const float4* xsq4  = reinterpret_cast<const float4*>(sXsq);
            const bool diag = (bi == bj);
            #pragma unroll 2
            for (int c4 = 0; c4 < 32; ++c4) {
                float4 dv = srow4[c4];
                float4 xq = xsq4[c4];
                float s0 = xq.x - 2.0f * dv.x;
                float s1 = xq.y - 2.0f * dv.y;
                float s2 = xq.z - 2.0f * dv.z;
                float s3 = xq.w - 2.0f * dv.w;
                int cb = c4 * 4;
                if (diag) {
                    if (cb == r)     s0 = 3.4e38f;
                    if (cb + 1 == r) s1 = 3.4e38f;
                    if (cb + 2 == r) s2 = 3.4e38f;
                    if (cb + 3 == r) s3 = 3.4e38f;
                }
                TOP10_INSERT(s0, j0 + cb,     v, id)
                TOP10_INSERT(s1, j0 + cb + 1, v, id)
                TOP10_INSERT(s2, j0 + cb + 2, v, id)
                TOP10_INSERT(s3, j0 + cb + 3, v, id)
            }
            float2* dst = &g_cand[((size_t)(i0 + r) * NTILE + bj) * Kn];
            #pragma unroll
            for (int k = 0; k < Kn; ++k)
                dst[k] = make_float2(v[k], __int_as_float(id[k]));
        } else {
            #pragma unroll 4
            for (int c = 0; c < 128; ++c) {
                float s = sXsq[128 + c] - 2.0f * stg[c * 132 + r];
                TOP10_INSERT(s, i0 + c, v, id)
            }
            float2* dst = &g_cand[((size_t)(j0 + r) * NTILE + bi) * Kn];
            #pragma unroll
            for (int k = 0; k < Kn; ++k)
                dst[k] = make_float2(v[k], __int_as_float(id[k]));
        }
    }
}

// ---------------- kernel 3: fused merge + loss + final reduction -----------
// 32-bit key: top 19 bits = ordered(d2) truncated, low 13 bits = idx.
// Truncation error on d2 <= ~0.03 (d2 ~ 450) -> negligible for selection/xd.
__device__ __forceinline__ uint32_t pack_key32(float2 p) {
    uint32_t u = __float_as_uint(p.x);
    u = (u & 0x80000000u) ? ~u : (u | 0x80000000u);
    return (u & 0xFFFFE000u) | ((uint32_t)__float_as_int(p.y) & 0x1FFFu);
}
__device__ __forceinline__ float unpack_val32(uint32_t k) {
    uint32_t u = k & 0xFFFFE000u;
    u = (u & 0x80000000u) ? (u & 0x7fffffffu) : ~u;
    return __uint_as_float(u);
}
#define CEX(a, b) { uint32_t _mn = min((a), (b)); \
                    uint32_t _mx = max((a), (b)); (a) = _mn; (b) = _mx; }
#define BSORT16(k)                                                             \
    _Pragma("unroll") for (int _d = 8; _d >= 1; _d >>= 1)                      \
        _Pragma("unroll") for (int _i = 0; _i < 16; ++_i)                      \
            if (!(_i & _d)) CEX(k[_i], k[_i + _d])

__global__ void __launch_bounds__(256) topk_loss_kernel(const float* __restrict__ Z,
                                                        float* __restrict__ out) {
    const int lane = threadIdx.x & 31;
    const int row  = blockIdx.x * 8 + (threadIdx.x >> 5);

    // ---- bitonic shuffle merge of 64 sorted-10 lists (u32 keys) ----
    uint32_t A[16], K[16];
    {
        const float2* la = &g_cand[((size_t)row * NTILE + lane) * Kn];
        const float2* lb = &g_cand[((size_t)row * NTILE + lane + 32) * Kn];
        uint32_t a[10], b[10];
        #pragma unroll
        for (int k = 0; k < Kn; ++k) { a[k] = pack_key32(la[k]); b[k] = pack_key32(lb[k]); }
        #pragma unroll
        for (int i = 0; i < 6; ++i)  K[i] = a[i];
        #pragma unroll
        for (int i = 6; i < 10; ++i) K[i] = min(a[i], b[15 - i]);
        #pragma unroll
        for (int i = 10; i < 16; ++i) K[i] = b[15 - i];
        BSORT16(K);
    }
    #pragma unroll
    for (int s = 1; s < 32; s <<= 1) {
        #pragma unroll
        for (int i = 0; i < 16; ++i)
            A[i] = __shfl_xor_sync(0xFFFFFFFFu, K[i], s);
        #pragma unroll
        for (int i = 0; i < 16; ++i)
            K[i] = min(K[i], A[15 - i]);
        BSORT16(K);
    }
    // all lanes now hold the global top-16 keys (we use 10)

    // ---- z distances + loss (x_dist from GEMM d2 values) ----
    const float2 zi = reinterpret_cast<const float2*>(Z + (size_t)row * 64)[lane];
    const float xsq_i = g_Xsq[row];
    float xd[Kn], zd[Kn];
    #pragma unroll
    for (int k = 0; k < Kn; ++k) {
        int nb = (int)(K[k] & 0x1FFFu);
        const float2 zn = reinterpret_cast<const float2*>(Z + (size_t)nb * 64)[lane];
        float d0 = zi.x - zn.x, d1 = zi.y - zn.y;
        float sz = fmaf(d0, d0, d1 * d1);
        #pragma unroll
        for (int o = 16; o > 0; o >>= 1) sz += __shfl_xor_sync(0xFFFFFFFFu, sz, o);
        zd[k] = sqrtf(sz);
        xd[k] = sqrtf(fmaxf(xsq_i + unpack_val32(K[k]), 0.0f));
    }
    if (lane == 0) {
        float xm = 0.0f, zm = 0.0f;
        #pragma unroll
        for (int k = 0; k < Kn; ++k) { xm = fmaxf(xm, xd[k]); zm = fmaxf(zm, zd[k]); }
        xm = fmaxf(xm, 1e-8f);
        zm = fmaxf(zm, 1e-8f);
        float s = 0.0f;
        #pragma unroll
        for (int k = 0; k < Kn; ++k) s += fabsf(xd[k] / xm - zd[k] / zm);
        g_rowsum[row] = s;
    }

    // ---- last-block deterministic final reduction ----
    __shared__ int sflag;
    __syncthreads();
    if (threadIdx.x == 0) {
        __threadfence();
        sflag = (atomicAdd(&g_done, 1) == gridDim.x - 1) ? 1 : 0;
    }
    __syncthreads();
    if (sflag) {
        __threadfence();
        __shared__ float sm[256];
        const int t = threadIdx.x;
        float s = 0.0f;
        for (int i = t; i < Nn; i += 256) s += g_rowsum[i];
        sm[t] = s;
        __syncthreads();
        for (int st = 128; st > 0; st >>= 1) {
            if (t < st) sm[t] += sm[t + st];
            __syncthreads();
        }
        if (t == 0) {
            out[0] = sm[0] / (float)(Nn * Kn);
            g_done = 0;                       // reset for next graph replay
        }
    }
}

// ---------------- launch ---------------------------------------------------
extern "C" void kernel_launch(void* const* d_in, const int* in_sizes, int n_in,
                              void* d_out, int out_size) {
    const float* z = (const float*)d_in[0];
    const float* X = (const float*)d_in[1];
    if (n_in >= 2 && in_sizes[0] != Nn * 64) {
        z = (const float*)d_in[1];
        X = (const float*)d_in[0];
    }
    float* out = (float*)d_out;

    cudaFuncSetAttribute(gemm_mma_kernel, cudaFuncAttributeMaxDynamicSharedMemorySize, SMEM_DYN);

    convert_kernel<<<Nn * 32 / 256, 256>>>(X);
    gemm_mma_kernel<<<NTRI, 256, SMEM_DYN>>>();
    topk_loss_kernel<<<Nn / 8, 256>>>(z, out);
}